// round 11
// baseline (speedup 1.0000x reference)
#include <cuda_runtime.h>
#include <math.h>

#define NN   131072      // total nodes
#define EE   1048576     // total edges
#define BB   128         // graphs
#define NPG  1024        // nodes per graph
#define DD   97          // total latent dim
#define KK   30          // sort-pool k
#define CAP  64          // max in-degree bucket capacity (Poisson(8): P(>64) ~ 0)
#define PNB  64          // nodes per block in pool kernel

// ---- scratch (device globals; no allocation allowed) ----
__device__ int   g_cnt[NN];                 // in-degree (fill cursor)
__device__ int   g_bkt [(size_t)NN * CAP];  // buckets: edge id by dst (for e2n)
__device__ int   g_bsrc[(size_t)NN * CAP];  // buckets: src node by dst (for pools)
__device__ float g_e2n[(size_t)NN * 32];    // pooled edge features per node
__device__ float g_za [(size_t)NN * 32];    // z ping
__device__ float g_zb [(size_t)NN * 32];    // z pong
__device__ float g_z3 [NN];                 // scalar z for hop 3
__device__ float g_feat[(size_t)NN * DD];   // concatenated hop outputs

// buffer selectors resolved in DEVICE code only
__device__ __forceinline__ float* zbuf(int which) {
    return which == 0 ? g_za : g_zb;
}

// ---------------------------------------------------------------------------
__global__ void zero_cnt_kernel() {
    int i = blockIdx.x * blockDim.x + threadIdx.x;
    if (i < NN) g_cnt[i] = 0;
}

// place each edge into its destination bucket; also cache src id
__global__ void fill_kernel(const int* __restrict__ src,
                            const int* __restrict__ dst) {
    int e = blockIdx.x * blockDim.x + threadIdx.x;
    if (e >= EE) return;
    int d = dst[e];
    int pos = atomicAdd(&g_cnt[d], 1);
    if (pos < CAP) {
        g_bkt [(size_t)d * CAP + pos] = e;
        g_bsrc[(size_t)d * CAP + pos] = src[e];
    }
}

// e2n: warp per node, lane = feature; gather-sum incident edge feature rows
// (unroll x4 for MLP)
__global__ void e2n_kernel(const float* __restrict__ edge_feat) {
    int gw   = (blockIdx.x * blockDim.x + threadIdx.x) >> 5;
    int lane = threadIdx.x & 31;
    if (gw >= NN) return;
    int dc = min(g_cnt[gw], CAP);
    const int* bp = g_bkt + (size_t)gw * CAP;
    float acc = 0.0f;
    int i = 0;
    for (; i + 4 <= dc; i += 4) {
        int e0 = bp[i], e1 = bp[i+1], e2 = bp[i+2], e3 = bp[i+3];
        float v0 = edge_feat[(size_t)e0 * 32 + lane];
        float v1 = edge_feat[(size_t)e1 * 32 + lane];
        float v2 = edge_feat[(size_t)e2 * 32 + lane];
        float v3 = edge_feat[(size_t)e3 * 32 + lane];
        acc += v0; acc += v1; acc += v2; acc += v3;
    }
    for (; i < dc; i++)
        acc += edge_feat[(size_t)bp[i] * 32 + lane];
    g_e2n[(size_t)gw * 32 + lane] = acc;
}

// z0 = [node_feat | e2n] @ W0  — register-tiled block GEMM.
// 512 blocks x 256 nodes (single wave at 4 blocks/SM); thread = 8 nodes x 4 ch.
__global__ void __launch_bounds__(256, 4)
mm0_kernel(const float* __restrict__ nf, const float* __restrict__ W0) {
    __shared__ float Ws[160 * 32];       // full weight matrix, 20KB
    __shared__ float Xs[32][257];        // f-major transposed chunk, pad 257
    int tid = threadIdx.x;
    for (int i = tid; i < 160 * 32; i += 256) Ws[i] = W0[i];

    int nbase = blockIdx.x * 256;
    int chg  = (tid & 7) * 4;            // channel group 0,4,...,28
    int ng   = (tid >> 3) * 8;           // node group 0,8,...,248
    int f    = tid & 31;                 // lane = feature (coalesced LDG)
    int nrow = tid >> 5;                 // 0..7

    float acc[8][4];
    #pragma unroll
    for (int m = 0; m < 8; m++)
        #pragma unroll
        for (int k = 0; k < 4; k++) acc[m][k] = 0.0f;

    for (int c = 0; c < 5; c++) {
        __syncthreads();
        int fg = c * 32 + f;
        #pragma unroll
        for (int i = 0; i < 32; i++) {
            int n = nrow + i * 8;
            Xs[f][n] = (fg < 128)
                ? nf[(size_t)(nbase + n) * 128 + fg]
                : g_e2n[(size_t)(nbase + n) * 32 + (fg - 128)];
        }
        __syncthreads();
        #pragma unroll
        for (int f2 = 0; f2 < 32; f2++) {
            float4 w = *(const float4*)&Ws[(c * 32 + f2) * 32 + chg];
            #pragma unroll
            for (int m = 0; m < 8; m++) {
                float x = Xs[f2][ng + m];
                acc[m][0] += x * w.x; acc[m][1] += x * w.y;
                acc[m][2] += x * w.z; acc[m][3] += x * w.w;
            }
        }
    }
    #pragma unroll
    for (int m = 0; m < 8; m++) {
        float4 o = make_float4(acc[m][0], acc[m][1], acc[m][2], acc[m][3]);
        *(float4*)&g_za[(size_t)(nbase + ng + m) * 32 + chg] = o;
    }
}

// pool(z)+z -> +bias -> /deg -> tanh -> feat slice, then block-tiled GEMM
// z_next = V @ Wn through smem. 64 nodes per 256-thread block.
__global__ void pool_kernel(int zin_which, int zout_which,
                            const float* __restrict__ bcur,
                            const float* __restrict__ Wn,
                            int foff, int scalar_next) {
    __shared__ float Ws[32 * 32];
    __shared__ float Vs[PNB][33];
    __shared__ float bs[32];
    __shared__ float sw[32];
    int tid = threadIdx.x;
    if (tid < 32) {
        bs[tid] = bcur[tid];
        if (scalar_next) sw[tid] = Wn[tid];
    }
    if (!scalar_next)
        for (int i = tid; i < 32 * 32; i += 256) Ws[i] = Wn[i];
    __syncthreads();

    const float* zin = zbuf(zin_which);
    int lane = tid & 31;
    int w    = tid >> 5;
    int nbase = blockIdx.x * PNB;

    #pragma unroll
    for (int r = 0; r < 8; r++) {
        int node = nbase + w * 8 + r;
        int deg = g_cnt[node];
        int dc  = min(deg, CAP);
        const int* bsp = g_bsrc + (size_t)node * CAP;
        float acc = zin[(size_t)node * 32 + lane];    // self term (A + I)
        int i = 0;
        for (; i + 4 <= dc; i += 4) {                 // unroll x4 for MLP
            int s0 = bsp[i], s1 = bsp[i+1], s2 = bsp[i+2], s3 = bsp[i+3];
            float v0 = zin[(size_t)s0 * 32 + lane];
            float v1 = zin[(size_t)s1 * 32 + lane];
            float v2 = zin[(size_t)s2 * 32 + lane];
            float v3 = zin[(size_t)s3 * 32 + lane];
            acc += v0; acc += v1; acc += v2; acc += v3;
        }
        for (; i < dc; i++)
            acc += zin[(size_t)bsp[i] * 32 + lane];
        float v = tanhf((acc + bs[lane]) / (float)(deg + 1));
        g_feat[(size_t)node * DD + foff + lane] = v;
        if (scalar_next) {
            float p = v * sw[lane];
            #pragma unroll
            for (int o = 16; o > 0; o >>= 1)
                p += __shfl_xor_sync(0xffffffffu, p, o);
            if (lane == 0) g_z3[node] = p;
        } else {
            Vs[w * 8 + r][lane] = v;
        }
    }
    if (scalar_next) return;
    __syncthreads();

    float* zout = zbuf(zout_which);
    int chg = (tid & 7) * 4;     // 4 output channels
    int n0  = (tid >> 3) * 2;    // 2 nodes
    float a[2][4] = {{0.f,0.f,0.f,0.f},{0.f,0.f,0.f,0.f}};
    #pragma unroll
    for (int t = 0; t < 32; t++) {
        float4 w4 = *(const float4*)&Ws[t * 32 + chg];
        float x0 = Vs[n0][t];
        float x1 = Vs[n0 + 1][t];
        a[0][0] += x0 * w4.x; a[0][1] += x0 * w4.y;
        a[0][2] += x0 * w4.z; a[0][3] += x0 * w4.w;
        a[1][0] += x1 * w4.x; a[1][1] += x1 * w4.y;
        a[1][2] += x1 * w4.z; a[1][3] += x1 * w4.w;
    }
    *(float4*)&zout[(size_t)(nbase + n0) * 32 + chg] =
        make_float4(a[0][0], a[0][1], a[0][2], a[0][3]);
    *(float4*)&zout[(size_t)(nbase + n0 + 1) * 32 + chg] =
        make_float4(a[1][0], a[1][1], a[1][2], a[1][3]);
}

// final hop: scalar pooling of z3, thread per node (z3 is 512KB -> L2 resident)
__global__ void pool_scalar_kernel(const float* __restrict__ b3) {
    int n = blockIdx.x * blockDim.x + threadIdx.x;
    if (n >= NN) return;
    int deg = g_cnt[n];
    int dc  = min(deg, CAP);
    const int* bsp = g_bsrc + (size_t)n * CAP;
    float acc = g_z3[n];
    int i = 0;
    for (; i + 4 <= dc; i += 4) {
        float v0 = g_z3[bsp[i]],   v1 = g_z3[bsp[i+1]];
        float v2 = g_z3[bsp[i+2]], v3 = g_z3[bsp[i+3]];
        acc += v0; acc += v1; acc += v2; acc += v3;
    }
    for (; i < dc; i++) acc += g_z3[bsp[i]];
    g_feat[(size_t)n * DD + 96] = tanhf((acc + b3[0]) / (float)(deg + 1));
}

// ---------------------------------------------------------------------------
// one block per graph: register-resident stable top-k (warp-shuffle argmax)
// -> gather -> conv1 -> relu -> maxpool2 -> conv2 -> relu -> dense -> relu
__global__ void tail_kernel(const float* __restrict__ w1, const float* __restrict__ b1,
                            const float* __restrict__ w2, const float* __restrict__ b2,
                            const float* __restrict__ wo, const float* __restrict__ bo,
                            float* __restrict__ out) {
    __shared__ float wv[8];
    __shared__ int   wi[8];
    __shared__ int   topi[KK];
    __shared__ float sp[KK * DD];
    __shared__ float s_w1[16 * DD];
    __shared__ float s_w2[32 * 16 * 5];
    __shared__ float o1[16 * 30];
    __shared__ float pl[16 * 15];
    __shared__ float o2[32 * 11];

    int b = blockIdx.x;
    int tid = threadIdx.x;
    int lane = tid & 31;

    // scores live in registers: thread owns indices tid + q*256
    float r[4];
    #pragma unroll
    for (int q = 0; q < 4; q++)
        r[q] = g_feat[(size_t)(b * NPG + tid + q * 256) * DD + 96];
    for (int i = tid; i < 16 * DD; i += 256) s_w1[i] = w1[i];
    for (int i = tid; i < 32 * 16 * 5; i += 256) s_w2[i] = w2[i];
    __syncthreads();

    // iterative argmax, stable (lowest index wins on ties)
    for (int k = 0; k < KK; k++) {
        float bv = -2.0f; int bi = NPG;
        #pragma unroll
        for (int q = 0; q < 4; q++) {        // indices increase with q
            if (r[q] > bv) { bv = r[q]; bi = tid + q * 256; }
        }
        #pragma unroll
        for (int o = 16; o > 0; o >>= 1) {
            float ov = __shfl_down_sync(0xffffffffu, bv, o);
            int   oi = __shfl_down_sync(0xffffffffu, bi, o);
            if (ov > bv || (ov == bv && oi < bi)) { bv = ov; bi = oi; }
        }
        if (lane == 0) { wv[tid >> 5] = bv; wi[tid >> 5] = bi; }
        __syncthreads();
        if (tid == 0) {
            #pragma unroll
            for (int u = 1; u < 8; u++)
                if (wv[u] > bv || (wv[u] == bv && wi[u] < bi)) { bv = wv[u]; bi = wi[u]; }
            topi[k] = bi;
        }
        __syncthreads();
        int bsel = topi[k];
        if ((bsel & 255) == tid) r[bsel >> 8] = -3.0f;   // remove selected
    }

    // gather the 30 selected rows
    for (int i = tid; i < KK * DD; i += 256) {
        int k = i / DD;
        int d = i - k * DD;
        sp[i] = g_feat[(size_t)(b * NPG + topi[k]) * DD + d];
    }
    __syncthreads();

    // conv1: [16, 30]
    for (int i = tid; i < 16 * 30; i += 256) {
        int c = i / 30;
        int pos = i - c * 30;
        float s = b1[c];
        for (int d = 0; d < DD; d++) s += sp[pos * DD + d] * s_w1[c * DD + d];
        o1[i] = fmaxf(s, 0.0f);
    }
    __syncthreads();

    // maxpool(2,2) -> [16, 15]
    for (int i = tid; i < 16 * 15; i += 256) {
        int c = i / 15;
        int pos = i - c * 15;
        pl[i] = fmaxf(o1[c * 30 + 2 * pos], o1[c * 30 + 2 * pos + 1]);
    }
    __syncthreads();

    // conv2: [32, 11]
    for (int i = tid; i < 32 * 11; i += 256) {
        int c = i / 11;
        int pos = i - c * 11;
        float s = b2[c];
        for (int ci = 0; ci < 16; ci++)
            for (int t = 0; t < 5; t++)
                s += pl[ci * 15 + pos + t] * s_w2[(c * 16 + ci) * 5 + t];
        o2[i] = fmaxf(s, 0.0f);
    }
    __syncthreads();

    // dense -> [2], relu
    if (tid < 2) {
        float s = bo[tid];
        for (int j = 0; j < 352; j++) s += o2[j] * wo[j * 2 + tid];
        out[b * 2 + tid] = fmaxf(s, 0.0f);
    }
}

// ---------------------------------------------------------------------------
extern "C" void kernel_launch(void* const* d_in, const int* in_sizes, int n_in,
                              void* d_out, int out_size) {
    const float* node_feat = (const float*)d_in[0];
    const float* edge_feat = (const float*)d_in[1];
    const int*   eidx      = (const int*)d_in[2];
    const int*   src = eidx;
    const int*   dst = eidx + EE;
    const float* W0 = (const float*)d_in[3];  const float* b0 = (const float*)d_in[4];
    const float* W1 = (const float*)d_in[5];  const float* b1 = (const float*)d_in[6];
    const float* W2 = (const float*)d_in[7];  const float* b2 = (const float*)d_in[8];
    const float* W3 = (const float*)d_in[9];  const float* b3 = (const float*)d_in[10];
    const float* w_conv1 = (const float*)d_in[11];
    const float* b_conv1 = (const float*)d_in[12];
    const float* w_conv2 = (const float*)d_in[13];
    const float* b_conv2 = (const float*)d_in[14];
    const float* w_out   = (const float*)d_in[15];
    const float* b_out   = (const float*)d_in[16];
    float* out = (float*)d_out;

    const int TPB = 256;
    const int warp_grid = (NN * 32 + TPB - 1) / TPB;   // warp-per-node kernels
    const int pool_grid = NN / PNB;                    // 2048 blocks

    zero_cnt_kernel<<<(NN + TPB - 1) / TPB, TPB>>>();
    fill_kernel<<<(EE + TPB - 1) / TPB, TPB>>>(src, dst);
    e2n_kernel<<<warp_grid, TPB>>>(edge_feat);
    mm0_kernel<<<NN / 256, TPB>>>(node_feat, W0);             // 512 blocks -> g_za
    pool_kernel<<<pool_grid, TPB>>>(0, 1, b0, W1,  0, 0);     // za->zb
    pool_kernel<<<pool_grid, TPB>>>(1, 0, b1, W2, 32, 0);     // zb->za
    pool_kernel<<<pool_grid, TPB>>>(0, 0, b2, W3, 64, 1);     // za->g_z3
    pool_scalar_kernel<<<(NN + TPB - 1) / TPB, TPB>>>(b3);    // hop3
    tail_kernel<<<BB, TPB>>>(w_conv1, b_conv1, w_conv2, b_conv2,
                             w_out, b_out, out);
}

// round 12
// speedup vs baseline: 1.0123x; 1.0123x over previous
#include <cuda_runtime.h>
#include <math.h>

#define NN   131072      // total nodes
#define EE   1048576     // total edges
#define BB   128         // graphs
#define NPG  1024        // nodes per graph
#define DD   97          // total latent dim
#define KK   30          // sort-pool k
#define CAP  64          // max in-degree bucket capacity (Poisson(8): P(>64) ~ 0)
#define PNB  64          // nodes per block in pool kernel

// ---- scratch (device globals; no allocation allowed) ----
__device__ int   g_cnt[NN];                 // in-degree (fill cursor)
__device__ int   g_bkt [(size_t)NN * CAP];  // buckets: edge id by dst (for e2n)
__device__ int   g_bsrc[(size_t)NN * CAP];  // buckets: src node by dst (for pools)
__device__ float g_za [(size_t)NN * 32];    // z ping
__device__ float g_zb [(size_t)NN * 32];    // z pong
__device__ float g_z3 [NN];                 // scalar z for hop 3
__device__ float g_feat[(size_t)NN * DD];   // concatenated hop outputs (ch 0..95)

// buffer selectors resolved in DEVICE code only
__device__ __forceinline__ float* zbuf(int which) {
    return which == 0 ? g_za : g_zb;
}

// ---------------------------------------------------------------------------
__global__ void zero_cnt_kernel() {
    int i = blockIdx.x * blockDim.x + threadIdx.x;
    if (i < NN) g_cnt[i] = 0;
}

// place each edge into its destination bucket; also cache src id
__global__ void fill_kernel(const int* __restrict__ src,
                            const int* __restrict__ dst) {
    int e = blockIdx.x * blockDim.x + threadIdx.x;
    if (e >= EE) return;
    int d = dst[e];
    int pos = atomicAdd(&g_cnt[d], 1);
    if (pos < CAP) {
        g_bkt [(size_t)d * CAP + pos] = e;
        g_bsrc[(size_t)d * CAP + pos] = src[e];
    }
}

// z0 = [node_feat | e2n] @ W0 — register-tiled block GEMM with e2n gather
// FUSED in (chunk 4 of K comes from an in-smem edge-feature pooling).
// block = 256 threads, 128 nodes; thread tile = 4 nodes x 4 channels.
__global__ void mm0_kernel(const float* __restrict__ nf,
                           const float* __restrict__ W0,
                           const float* __restrict__ edge_feat) {
    __shared__ float Ws[160 * 32];       // full weight matrix, 20KB
    __shared__ float Xs[32][133];        // f-major transposed chunk, pad=133
    __shared__ float E2s[128][33];       // e2n rows for this block's nodes
    int tid = threadIdx.x;
    int lane = tid & 31;
    int w    = tid >> 5;
    for (int i = tid; i < 160 * 32; i += 256) Ws[i] = W0[i];

    int nbase = blockIdx.x * 128;

    // phase A: e2n gather — warp w pools edge features for nodes w*16..w*16+15
    for (int r = 0; r < 16; r++) {
        int nl = w * 16 + r;
        int node = nbase + nl;
        int dc = min(g_cnt[node], CAP);
        const int* bp = g_bkt + (size_t)node * CAP;
        float acc = 0.0f;
        for (int i = 0; i < dc; i++)
            acc += edge_feat[(size_t)bp[i] * 32 + lane];
        E2s[nl][lane] = acc;
    }

    int chg  = (tid & 7) * 4;            // channel group 0,4,...,28
    int ng   = (tid >> 3) * 4;           // node group 0,4,...,124
    int nrow = tid >> 5;                 // 0..7

    float acc[4][4];
    #pragma unroll
    for (int m = 0; m < 4; m++)
        #pragma unroll
        for (int k = 0; k < 4; k++) acc[m][k] = 0.0f;

    // chunks 0..3: node_feat through Xs transpose staging
    for (int c = 0; c < 4; c++) {
        __syncthreads();
        int fg = c * 32 + lane;
        #pragma unroll
        for (int i = 0; i < 16; i++) {
            int n = nrow + i * 8;
            Xs[lane][n] = nf[(size_t)(nbase + n) * 128 + fg];
        }
        __syncthreads();
        #pragma unroll
        for (int f2 = 0; f2 < 32; f2++) {
            float4 w4 = *(const float4*)&Ws[(c * 32 + f2) * 32 + chg];
            float x0 = Xs[f2][ng + 0];
            float x1 = Xs[f2][ng + 1];
            float x2 = Xs[f2][ng + 2];
            float x3 = Xs[f2][ng + 3];
            acc[0][0] += x0 * w4.x; acc[0][1] += x0 * w4.y;
            acc[0][2] += x0 * w4.z; acc[0][3] += x0 * w4.w;
            acc[1][0] += x1 * w4.x; acc[1][1] += x1 * w4.y;
            acc[1][2] += x1 * w4.z; acc[1][3] += x1 * w4.w;
            acc[2][0] += x2 * w4.x; acc[2][1] += x2 * w4.y;
            acc[2][2] += x2 * w4.z; acc[2][3] += x2 * w4.w;
            acc[3][0] += x3 * w4.x; acc[3][1] += x3 * w4.y;
            acc[3][2] += x3 * w4.z; acc[3][3] += x3 * w4.w;
        }
    }
    // chunk 4: e2n features straight from E2s (rows (ng+m)*33+f2 -> 4 distinct
    // banks x 8-way broadcast, conflict-free)
    __syncthreads();
    #pragma unroll
    for (int f2 = 0; f2 < 32; f2++) {
        float4 w4 = *(const float4*)&Ws[(128 + f2) * 32 + chg];
        float x0 = E2s[ng + 0][f2];
        float x1 = E2s[ng + 1][f2];
        float x2 = E2s[ng + 2][f2];
        float x3 = E2s[ng + 3][f2];
        acc[0][0] += x0 * w4.x; acc[0][1] += x0 * w4.y;
        acc[0][2] += x0 * w4.z; acc[0][3] += x0 * w4.w;
        acc[1][0] += x1 * w4.x; acc[1][1] += x1 * w4.y;
        acc[1][2] += x1 * w4.z; acc[1][3] += x1 * w4.w;
        acc[2][0] += x2 * w4.x; acc[2][1] += x2 * w4.y;
        acc[2][2] += x2 * w4.z; acc[2][3] += x2 * w4.w;
        acc[3][0] += x3 * w4.x; acc[3][1] += x3 * w4.y;
        acc[3][2] += x3 * w4.z; acc[3][3] += x3 * w4.w;
    }
    #pragma unroll
    for (int m = 0; m < 4; m++) {
        float4 o = make_float4(acc[m][0], acc[m][1], acc[m][2], acc[m][3]);
        *(float4*)&g_za[(size_t)(nbase + ng + m) * 32 + chg] = o;
    }
}

// pool(z)+z -> +bias -> /deg -> tanh -> feat slice, then block-tiled GEMM
// z_next = V @ Wn through smem. 64 nodes per 256-thread block. (R10 shape.)
__global__ void pool_kernel(int zin_which, int zout_which,
                            const float* __restrict__ bcur,
                            const float* __restrict__ Wn,
                            int foff, int scalar_next) {
    __shared__ float Ws[32 * 32];
    __shared__ float Vs[PNB][33];
    __shared__ float bs[32];
    __shared__ float sw[32];
    int tid = threadIdx.x;
    if (tid < 32) {
        bs[tid] = bcur[tid];
        if (scalar_next) sw[tid] = Wn[tid];
    }
    if (!scalar_next)
        for (int i = tid; i < 32 * 32; i += 256) Ws[i] = Wn[i];
    __syncthreads();

    const float* zin = zbuf(zin_which);
    int lane = tid & 31;
    int w    = tid >> 5;
    int nbase = blockIdx.x * PNB;

    #pragma unroll
    for (int r = 0; r < 8; r++) {
        int node = nbase + w * 8 + r;
        int deg = g_cnt[node];
        int dc  = min(deg, CAP);
        const int* bsp = g_bsrc + (size_t)node * CAP;
        float acc = zin[(size_t)node * 32 + lane];    // self term (A + I)
        for (int i = 0; i < dc; i++)
            acc += zin[(size_t)bsp[i] * 32 + lane];   // coalesced 128B row
        float v = tanhf((acc + bs[lane]) / (float)(deg + 1));
        g_feat[(size_t)node * DD + foff + lane] = v;
        if (scalar_next) {
            float p = v * sw[lane];
            #pragma unroll
            for (int o = 16; o > 0; o >>= 1)
                p += __shfl_xor_sync(0xffffffffu, p, o);
            if (lane == 0) g_z3[node] = p;
        } else {
            Vs[w * 8 + r][lane] = v;
        }
    }
    if (scalar_next) return;
    __syncthreads();

    float* zout = zbuf(zout_which);
    int chg = (tid & 7) * 4;     // 4 output channels
    int n0  = (tid >> 3) * 2;    // 2 nodes
    float a[2][4] = {{0.f,0.f,0.f,0.f},{0.f,0.f,0.f,0.f}};
    #pragma unroll
    for (int t = 0; t < 32; t++) {
        float4 w4 = *(const float4*)&Ws[t * 32 + chg];
        float x0 = Vs[n0][t];
        float x1 = Vs[n0 + 1][t];
        a[0][0] += x0 * w4.x; a[0][1] += x0 * w4.y;
        a[0][2] += x0 * w4.z; a[0][3] += x0 * w4.w;
        a[1][0] += x1 * w4.x; a[1][1] += x1 * w4.y;
        a[1][2] += x1 * w4.z; a[1][3] += x1 * w4.w;
    }
    *(float4*)&zout[(size_t)(nbase + n0) * 32 + chg] =
        make_float4(a[0][0], a[0][1], a[0][2], a[0][3]);
    *(float4*)&zout[(size_t)(nbase + n0 + 1) * 32 + chg] =
        make_float4(a[1][0], a[1][1], a[1][2], a[1][3]);
}

// ---------------------------------------------------------------------------
// one block per graph. Now ALSO computes hop-3 scores (pool of g_z3 + tanh)
// in-block (same summation order as before -> bit-identical), then stable
// top-k -> gather -> conv1 -> relu -> maxpool2 -> conv2 -> relu -> dense.
__global__ void tail_kernel(const float* __restrict__ w1, const float* __restrict__ b1,
                            const float* __restrict__ w2, const float* __restrict__ b2,
                            const float* __restrict__ wo, const float* __restrict__ bo,
                            const float* __restrict__ b3,
                            float* __restrict__ out) {
    __shared__ float osc[NPG];           // pristine hop-3 scores
    __shared__ float wv[8];
    __shared__ int   wi[8];
    __shared__ int   topi[KK];
    __shared__ float sp[KK * DD];
    __shared__ float s_w1[16 * DD];
    __shared__ float s_w2[32 * 16 * 5];
    __shared__ float o1[16 * 30];
    __shared__ float pl[16 * 15];
    __shared__ float o2[32 * 11];

    int b = blockIdx.x;
    int tid = threadIdx.x;
    int lane = tid & 31;
    float bias3 = b3[0];

    // hop-3 scalar pooling for this graph's nodes (4 per thread)
    #pragma unroll
    for (int q = 0; q < 4; q++) {
        int i = tid + q * 256;
        int n = b * NPG + i;
        int deg = g_cnt[n];
        int dc  = min(deg, CAP);
        const int* bsp = g_bsrc + (size_t)n * CAP;
        float acc = g_z3[n];
        for (int j = 0; j < dc; j++) acc += g_z3[bsp[j]];
        osc[i] = tanhf((acc + bias3) / (float)(deg + 1));
    }
    for (int i = tid; i < 16 * DD; i += 256) s_w1[i] = w1[i];
    for (int i = tid; i < 32 * 16 * 5; i += 256) s_w2[i] = w2[i];
    __syncthreads();

    // scores to registers: thread owns indices tid + q*256
    float r[4];
    #pragma unroll
    for (int q = 0; q < 4; q++) r[q] = osc[tid + q * 256];

    // iterative argmax, stable (lowest index wins on ties)
    for (int k = 0; k < KK; k++) {
        float bv = -2.0f; int bi = NPG;
        #pragma unroll
        for (int q = 0; q < 4; q++) {        // indices increase with q
            if (r[q] > bv) { bv = r[q]; bi = tid + q * 256; }
        }
        #pragma unroll
        for (int o = 16; o > 0; o >>= 1) {
            float ov = __shfl_down_sync(0xffffffffu, bv, o);
            int   oi = __shfl_down_sync(0xffffffffu, bi, o);
            if (ov > bv || (ov == bv && oi < bi)) { bv = ov; bi = oi; }
        }
        if (lane == 0) { wv[tid >> 5] = bv; wi[tid >> 5] = bi; }
        __syncthreads();
        if (tid == 0) {
            #pragma unroll
            for (int u = 1; u < 8; u++)
                if (wv[u] > bv || (wv[u] == bv && wi[u] < bi)) { bv = wv[u]; bi = wi[u]; }
            topi[k] = bi;
        }
        __syncthreads();
        int bsel = topi[k];
        if ((bsel & 255) == tid) r[bsel >> 8] = -3.0f;   // remove selected
    }

    // gather the 30 selected rows; channel 96 comes from osc (pristine)
    for (int i = tid; i < KK * DD; i += 256) {
        int k = i / DD;
        int d = i - k * DD;
        sp[i] = (d == 96) ? osc[topi[k]]
                          : g_feat[(size_t)(b * NPG + topi[k]) * DD + d];
    }
    __syncthreads();

    // conv1: [16, 30]
    for (int i = tid; i < 16 * 30; i += 256) {
        int c = i / 30;
        int pos = i - c * 30;
        float s = b1[c];
        for (int d = 0; d < DD; d++) s += sp[pos * DD + d] * s_w1[c * DD + d];
        o1[i] = fmaxf(s, 0.0f);
    }
    __syncthreads();

    // maxpool(2,2) -> [16, 15]
    for (int i = tid; i < 16 * 15; i += 256) {
        int c = i / 15;
        int pos = i - c * 15;
        pl[i] = fmaxf(o1[c * 30 + 2 * pos], o1[c * 30 + 2 * pos + 1]);
    }
    __syncthreads();

    // conv2: [32, 11]
    for (int i = tid; i < 32 * 11; i += 256) {
        int c = i / 11;
        int pos = i - c * 11;
        float s = b2[c];
        for (int ci = 0; ci < 16; ci++)
            for (int t = 0; t < 5; t++)
                s += pl[ci * 15 + pos + t] * s_w2[(c * 16 + ci) * 5 + t];
        o2[i] = fmaxf(s, 0.0f);
    }
    __syncthreads();

    // dense -> [2], relu
    if (tid < 2) {
        float s = bo[tid];
        for (int j = 0; j < 352; j++) s += o2[j] * wo[j * 2 + tid];
        out[b * 2 + tid] = fmaxf(s, 0.0f);
    }
}

// ---------------------------------------------------------------------------
extern "C" void kernel_launch(void* const* d_in, const int* in_sizes, int n_in,
                              void* d_out, int out_size) {
    const float* node_feat = (const float*)d_in[0];
    const float* edge_feat = (const float*)d_in[1];
    const int*   eidx      = (const int*)d_in[2];
    const int*   src = eidx;
    const int*   dst = eidx + EE;
    const float* W0 = (const float*)d_in[3];  const float* b0 = (const float*)d_in[4];
    const float* W1 = (const float*)d_in[5];  const float* b1 = (const float*)d_in[6];
    const float* W2 = (const float*)d_in[7];  const float* b2 = (const float*)d_in[8];
    const float* W3 = (const float*)d_in[9];  const float* b3 = (const float*)d_in[10];
    const float* w_conv1 = (const float*)d_in[11];
    const float* b_conv1 = (const float*)d_in[12];
    const float* w_conv2 = (const float*)d_in[13];
    const float* b_conv2 = (const float*)d_in[14];
    const float* w_out   = (const float*)d_in[15];
    const float* b_out   = (const float*)d_in[16];
    float* out = (float*)d_out;

    const int TPB = 256;
    const int pool_grid = NN / PNB;                    // 2048 blocks

    zero_cnt_kernel<<<(NN + TPB - 1) / TPB, TPB>>>();
    fill_kernel<<<(EE + TPB - 1) / TPB, TPB>>>(src, dst);
    mm0_kernel<<<NN / 128, TPB>>>(node_feat, W0, edge_feat);  // e2n fused -> g_za
    pool_kernel<<<pool_grid, TPB>>>(0, 1, b0, W1,  0, 0);     // za->zb
    pool_kernel<<<pool_grid, TPB>>>(1, 0, b1, W2, 32, 0);     // zb->za
    pool_kernel<<<pool_grid, TPB>>>(0, 0, b2, W3, 64, 1);     // za->g_z3
    tail_kernel<<<BB, TPB>>>(w_conv1, b_conv1, w_conv2, b_conv2,
                             w_out, b_out, b3, out);          // hop3 fused
}

// round 15
// speedup vs baseline: 1.0258x; 1.0133x over previous
#include <cuda_runtime.h>
#include <math.h>

#define NN   131072      // total nodes
#define EE   1048576     // total edges
#define BB   128         // graphs
#define NPG  1024        // nodes per graph
#define DD   97          // total latent dim
#define KK   30          // sort-pool k
#define CAP  64          // max in-degree bucket capacity (Poisson(8): P(>64) ~ 0)
#define PNB  64          // nodes per block in pool kernel

// ---- scratch (device globals; no allocation allowed) ----
__device__ int   g_cnt[NN];                 // in-degree (fill cursor)
__device__ int   g_bkt [(size_t)NN * CAP];  // buckets: edge id by dst (for e2n)
__device__ int   g_bsrc[(size_t)NN * CAP];  // buckets: src node by dst (for pools)
__device__ float g_e2n[(size_t)NN * 32];    // pooled edge features per node
__device__ float g_za [(size_t)NN * 32];    // z ping
__device__ float g_zb [(size_t)NN * 32];    // z pong
__device__ float g_z3 [NN];                 // scalar z for hop 3
__device__ float g_feat[(size_t)NN * DD];   // concatenated hop outputs (ch 0..95)

// buffer selectors resolved in DEVICE code only
__device__ __forceinline__ float* zbuf(int which) {
    return which == 0 ? g_za : g_zb;
}

// ---------------------------------------------------------------------------
__global__ void zero_cnt_kernel() {
    int i = blockIdx.x * blockDim.x + threadIdx.x;
    if (i < NN) g_cnt[i] = 0;
}

// place each edge into its destination bucket; also cache src id
__global__ void fill_kernel(const int* __restrict__ src,
                            const int* __restrict__ dst) {
    int e = blockIdx.x * blockDim.x + threadIdx.x;
    if (e >= EE) return;
    int d = dst[e];
    int pos = atomicAdd(&g_cnt[d], 1);
    if (pos < CAP) {
        g_bkt [(size_t)d * CAP + pos] = e;
        g_bsrc[(size_t)d * CAP + pos] = src[e];
    }
}

// 8-wide batched gather-sum of 32-float rows: indices clamped to slot 0 for
// the out-of-range tail (address always valid), loads issued back-to-back
// (MLP=8), masked via select, tree-added.
__device__ __forceinline__ float gather8(const float* __restrict__ rows,
                                         const int* __restrict__ bsp,
                                         int dc, int lane) {
    float acc = 0.0f;
    for (int base = 0; base < dc; base += 8) {
        int rem = dc - base;
        int idx[8];
        #pragma unroll
        for (int u = 0; u < 8; u++)
            idx[u] = bsp[base + (u < rem ? u : 0)];
        float v[8];
        #pragma unroll
        for (int u = 0; u < 8; u++)
            v[u] = rows[(size_t)idx[u] * 32 + lane];
        #pragma unroll
        for (int u = 0; u < 8; u++)
            if (u >= rem) v[u] = 0.0f;
        acc += ((v[0] + v[1]) + (v[2] + v[3])) + ((v[4] + v[5]) + (v[6] + v[7]));
    }
    return acc;
}

// e2n: warp per node, lane = feature; batched gather of edge feature rows
__global__ void e2n_kernel(const float* __restrict__ edge_feat) {
    int gw   = (blockIdx.x * blockDim.x + threadIdx.x) >> 5;
    int lane = threadIdx.x & 31;
    if (gw >= NN) return;
    int dc = min(g_cnt[gw], CAP);
    const int* bp = g_bkt + (size_t)gw * CAP;
    g_e2n[(size_t)gw * 32 + lane] = gather8(edge_feat, bp, dc, lane);
}

// z0 = [node_feat | e2n] @ W0  — register-tiled block GEMM (R10 shape).
// block = 256 threads, 128 nodes; thread tile = 4 nodes x 4 channels.
__global__ void mm0_kernel(const float* __restrict__ nf,
                           const float* __restrict__ W0) {
    __shared__ float Ws[160 * 32];       // full weight matrix, 20KB
    __shared__ float Xs[32][133];        // f-major transposed chunk, pad=133
    int tid = threadIdx.x;
    for (int i = tid; i < 160 * 32; i += 256) Ws[i] = W0[i];

    int nbase = blockIdx.x * 128;
    int chg = (tid & 7) * 4;             // channel group 0,4,...,28
    int ng  = (tid >> 3) * 4;            // node group 0,4,...,124
    int f    = tid & 31;                 // lane = feature (coalesced LDG)
    int nrow = tid >> 5;                 // 0..7

    float acc[4][4];
    #pragma unroll
    for (int m = 0; m < 4; m++)
        #pragma unroll
        for (int k = 0; k < 4; k++) acc[m][k] = 0.0f;

    for (int c = 0; c < 5; c++) {
        __syncthreads();
        int fg = c * 32 + f;
        #pragma unroll
        for (int i = 0; i < 16; i++) {
            int n = nrow + i * 8;
            Xs[f][n] = (fg < 128)
                ? nf[(size_t)(nbase + n) * 128 + fg]
                : g_e2n[(size_t)(nbase + n) * 32 + (fg - 128)];
        }
        __syncthreads();
        #pragma unroll
        for (int f2 = 0; f2 < 32; f2++) {
            float4 w = *(const float4*)&Ws[(c * 32 + f2) * 32 + chg];
            float x0 = Xs[f2][ng + 0];
            float x1 = Xs[f2][ng + 1];
            float x2 = Xs[f2][ng + 2];
            float x3 = Xs[f2][ng + 3];
            acc[0][0] += x0 * w.x; acc[0][1] += x0 * w.y;
            acc[0][2] += x0 * w.z; acc[0][3] += x0 * w.w;
            acc[1][0] += x1 * w.x; acc[1][1] += x1 * w.y;
            acc[1][2] += x1 * w.z; acc[1][3] += x1 * w.w;
            acc[2][0] += x2 * w.x; acc[2][1] += x2 * w.y;
            acc[2][2] += x2 * w.z; acc[2][3] += x2 * w.w;
            acc[3][0] += x3 * w.x; acc[3][1] += x3 * w.y;
            acc[3][2] += x3 * w.z; acc[3][3] += x3 * w.w;
        }
    }
    #pragma unroll
    for (int m = 0; m < 4; m++) {
        float4 o = make_float4(acc[m][0], acc[m][1], acc[m][2], acc[m][3]);
        *(float4*)&g_za[(size_t)(nbase + ng + m) * 32 + chg] = o;
    }
}

// pool(z)+z -> +bias -> /deg -> tanh -> feat slice, then block-tiled GEMM
// z_next = V @ Wn through smem. 64 nodes per 256-thread block. Gather is
// 8-wide batched (MLP=8).
__global__ void pool_kernel(int zin_which, int zout_which,
                            const float* __restrict__ bcur,
                            const float* __restrict__ Wn,
                            int foff, int scalar_next) {
    __shared__ float Ws[32 * 32];
    __shared__ float Vs[PNB][33];
    __shared__ float bs[32];
    __shared__ float sw[32];
    int tid = threadIdx.x;
    if (tid < 32) {
        bs[tid] = bcur[tid];
        if (scalar_next) sw[tid] = Wn[tid];
    }
    if (!scalar_next)
        for (int i = tid; i < 32 * 32; i += 256) Ws[i] = Wn[i];
    __syncthreads();

    const float* zin = zbuf(zin_which);
    int lane = tid & 31;
    int w    = tid >> 5;
    int nbase = blockIdx.x * PNB;

    #pragma unroll
    for (int r = 0; r < 8; r++) {
        int node = nbase + w * 8 + r;
        int deg = g_cnt[node];
        int dc  = min(deg, CAP);
        const int* bsp = g_bsrc + (size_t)node * CAP;
        float acc = zin[(size_t)node * 32 + lane]     // self term (A + I)
                  + gather8(zin, bsp, dc, lane);
        float v = tanhf((acc + bs[lane]) / (float)(deg + 1));
        g_feat[(size_t)node * DD + foff + lane] = v;
        if (scalar_next) {
            float p = v * sw[lane];
            #pragma unroll
            for (int o = 16; o > 0; o >>= 1)
                p += __shfl_xor_sync(0xffffffffu, p, o);
            if (lane == 0) g_z3[node] = p;
        } else {
            Vs[w * 8 + r][lane] = v;
        }
    }
    if (scalar_next) return;
    __syncthreads();

    float* zout = zbuf(zout_which);
    int chg = (tid & 7) * 4;     // 4 output channels
    int n0  = (tid >> 3) * 2;    // 2 nodes
    float a[2][4] = {{0.f,0.f,0.f,0.f},{0.f,0.f,0.f,0.f}};
    #pragma unroll
    for (int t = 0; t < 32; t++) {
        float4 w4 = *(const float4*)&Ws[t * 32 + chg];
        float x0 = Vs[n0][t];
        float x1 = Vs[n0 + 1][t];
        a[0][0] += x0 * w4.x; a[0][1] += x0 * w4.y;
        a[0][2] += x0 * w4.z; a[0][3] += x0 * w4.w;
        a[1][0] += x1 * w4.x; a[1][1] += x1 * w4.y;
        a[1][2] += x1 * w4.z; a[1][3] += x1 * w4.w;
    }
    *(float4*)&zout[(size_t)(nbase + n0) * 32 + chg] =
        make_float4(a[0][0], a[0][1], a[0][2], a[0][3]);
    *(float4*)&zout[(size_t)(nbase + n0 + 1) * 32 + chg] =
        make_float4(a[1][0], a[1][1], a[1][2], a[1][3]);
}

// ---------------------------------------------------------------------------
// one block per graph. Computes hop-3 scores in-block (same summation order as
// the old pool_scalar kernel -> bit-identical), then stable top-k -> gather ->
// conv1 -> relu -> maxpool2 -> conv2 -> relu -> dense -> relu.
__global__ void tail_kernel(const float* __restrict__ w1, const float* __restrict__ b1,
                            const float* __restrict__ w2, const float* __restrict__ b2,
                            const float* __restrict__ wo, const float* __restrict__ bo,
                            const float* __restrict__ b3,
                            float* __restrict__ out) {
    __shared__ float osc[NPG];           // pristine hop-3 scores
    __shared__ float wv[8];
    __shared__ int   wi[8];
    __shared__ int   topi[KK];
    __shared__ float sp[KK * DD];
    __shared__ float s_w1[16 * DD];
    __shared__ float s_w2[32 * 16 * 5];
    __shared__ float o1[16 * 30];
    __shared__ float pl[16 * 15];
    __shared__ float o2[32 * 11];

    int b = blockIdx.x;
    int tid = threadIdx.x;
    int lane = tid & 31;
    float bias3 = b3[0];

    // hop-3 scalar pooling for this graph's nodes (4 per thread)
    #pragma unroll
    for (int q = 0; q < 4; q++) {
        int i = tid + q * 256;
        int n = b * NPG + i;
        int deg = g_cnt[n];
        int dc  = min(deg, CAP);
        const int* bsp = g_bsrc + (size_t)n * CAP;
        float acc = g_z3[n];
        for (int j = 0; j < dc; j++) acc += g_z3[bsp[j]];
        osc[i] = tanhf((acc + bias3) / (float)(deg + 1));
    }
    for (int i = tid; i < 16 * DD; i += 256) s_w1[i] = w1[i];
    for (int i = tid; i < 32 * 16 * 5; i += 256) s_w2[i] = w2[i];
    __syncthreads();

    // scores to registers: thread owns indices tid + q*256
    float r[4];
    #pragma unroll
    for (int q = 0; q < 4; q++) r[q] = osc[tid + q * 256];

    // iterative argmax, stable (lowest index wins on ties)
    for (int k = 0; k < KK; k++) {
        float bv = -2.0f; int bi = NPG;
        #pragma unroll
        for (int q = 0; q < 4; q++) {        // indices increase with q
            if (r[q] > bv) { bv = r[q]; bi = tid + q * 256; }
        }
        #pragma unroll
        for (int o = 16; o > 0; o >>= 1) {
            float ov = __shfl_down_sync(0xffffffffu, bv, o);
            int   oi = __shfl_down_sync(0xffffffffu, bi, o);
            if (ov > bv || (ov == bv && oi < bi)) { bv = ov; bi = oi; }
        }
        if (lane == 0) { wv[tid >> 5] = bv; wi[tid >> 5] = bi; }
        __syncthreads();
        if (tid == 0) {
            #pragma unroll
            for (int u = 1; u < 8; u++)
                if (wv[u] > bv || (wv[u] == bv && wi[u] < bi)) { bv = wv[u]; bi = wi[u]; }
            topi[k] = bi;
        }
        __syncthreads();
        int bsel = topi[k];
        if ((bsel & 255) == tid) r[bsel >> 8] = -3.0f;   // remove selected
    }

    // gather the 30 selected rows; channel 96 comes from osc (pristine)
    for (int i = tid; i < KK * DD; i += 256) {
        int k = i / DD;
        int d = i - k * DD;
        sp[i] = (d == 96) ? osc[topi[k]]
                          : g_feat[(size_t)(b * NPG + topi[k]) * DD + d];
    }
    __syncthreads();

    // conv1: [16, 30]
    for (int i = tid; i < 16 * 30; i += 256) {
        int c = i / 30;
        int pos = i - c * 30;
        float s = b1[c];
        for (int d = 0; d < DD; d++) s += sp[pos * DD + d] * s_w1[c * DD + d];
        o1[i] = fmaxf(s, 0.0f);
    }
    __syncthreads();

    // maxpool(2,2) -> [16, 15]
    for (int i = tid; i < 16 * 15; i += 256) {
        int c = i / 15;
        int pos = i - c * 15;
        pl[i] = fmaxf(o1[c * 30 + 2 * pos], o1[c * 30 + 2 * pos + 1]);
    }
    __syncthreads();

    // conv2: [32, 11]
    for (int i = tid; i < 32 * 11; i += 256) {
        int c = i / 11;
        int pos = i - c * 11;
        float s = b2[c];
        for (int ci = 0; ci < 16; ci++)
            for (int t = 0; t < 5; t++)
                s += pl[ci * 15 + pos + t] * s_w2[(c * 16 + ci) * 5 + t];
        o2[i] = fmaxf(s, 0.0f);
    }
    __syncthreads();

    // dense -> [2], relu
    if (tid < 2) {
        float s = bo[tid];
        for (int j = 0; j < 352; j++) s += o2[j] * wo[j * 2 + tid];
        out[b * 2 + tid] = fmaxf(s, 0.0f);
    }
}

// ---------------------------------------------------------------------------
extern "C" void kernel_launch(void* const* d_in, const int* in_sizes, int n_in,
                              void* d_out, int out_size) {
    const float* node_feat = (const float*)d_in[0];
    const float* edge_feat = (const float*)d_in[1];
    const int*   eidx      = (const int*)d_in[2];
    const int*   src = eidx;
    const int*   dst = eidx + EE;
    const float* W0 = (const float*)d_in[3];  const float* b0 = (const float*)d_in[4];
    const float* W1 = (const float*)d_in[5];  const float* b1 = (const float*)d_in[6];
    const float* W2 = (const float*)d_in[7];  const float* b2 = (const float*)d_in[8];
    const float* W3 = (const float*)d_in[9];  const float* b3 = (const float*)d_in[10];
    const float* w_conv1 = (const float*)d_in[11];
    const float* b_conv1 = (const float*)d_in[12];
    const float* w_conv2 = (const float*)d_in[13];
    const float* b_conv2 = (const float*)d_in[14];
    const float* w_out   = (const float*)d_in[15];
    const float* b_out   = (const float*)d_in[16];
    float* out = (float*)d_out;

    const int TPB = 256;
    const int warp_grid = (NN * 32 + TPB - 1) / TPB;   // warp-per-node kernels
    const int pool_grid = NN / PNB;                    // 2048 blocks

    zero_cnt_kernel<<<(NN + TPB - 1) / TPB, TPB>>>();
    fill_kernel<<<(EE + TPB - 1) / TPB, TPB>>>(src, dst);
    e2n_kernel<<<warp_grid, TPB>>>(edge_feat);
    mm0_kernel<<<NN / 128, TPB>>>(node_feat, W0);             // -> g_za
    pool_kernel<<<pool_grid, TPB>>>(0, 1, b0, W1,  0, 0);     // za->zb
    pool_kernel<<<pool_grid, TPB>>>(1, 0, b1, W2, 32, 0);     // zb->za
    pool_kernel<<<pool_grid, TPB>>>(0, 0, b2, W3, 64, 1);     // za->g_z3
    tail_kernel<<<BB, TPB>>>(w_conv1, b_conv1, w_conv2, b_conv2,
                             w_out, b_out, b3, out);          // hop3 fused
}

// round 16
// speedup vs baseline: 1.0264x; 1.0006x over previous
#include <cuda_runtime.h>
#include <math.h>

#define NN   131072      // total nodes
#define EE   1048576     // total edges
#define BB   128         // graphs
#define NPG  1024        // nodes per graph
#define DD   97          // total latent dim
#define KK   30          // sort-pool k
#define CAP  64          // max in-degree bucket capacity (Poisson(8): P(>64) ~ 0)
#define PNB  64          // nodes per block in pool kernel

// ---- scratch (device globals; no allocation allowed) ----
__device__ int   g_cnt[NN];                 // in-degree (fill cursor)
__device__ int   g_bkt [(size_t)NN * CAP];  // buckets: edge id by dst (for e2n)
__device__ int   g_bsrc[(size_t)NN * CAP];  // buckets: src node by dst (for pools)
__device__ float g_e2n[(size_t)NN * 32];    // pooled edge features per node
__device__ float g_za [(size_t)NN * 32];    // z ping
__device__ float g_zb [(size_t)NN * 32];    // z pong
__device__ float g_z3 [NN];                 // scalar z for hop 3
__device__ float g_feat[(size_t)NN * DD];   // concatenated hop outputs

// buffer selectors resolved in DEVICE code only
__device__ __forceinline__ float* zbuf(int which) {
    return which == 0 ? g_za : g_zb;
}

// ---------------------------------------------------------------------------
__global__ void zero_cnt_kernel() {
    int i = blockIdx.x * blockDim.x + threadIdx.x;
    if (i < NN) g_cnt[i] = 0;
}

// place each edge into its destination bucket; also cache src id
__global__ void fill_kernel(const int* __restrict__ src,
                            const int* __restrict__ dst) {
    int e = blockIdx.x * blockDim.x + threadIdx.x;
    if (e >= EE) return;
    int d = dst[e];
    int pos = atomicAdd(&g_cnt[d], 1);
    if (pos < CAP) {
        g_bkt [(size_t)d * CAP + pos] = e;
        g_bsrc[(size_t)d * CAP + pos] = src[e];
    }
}

// 8-wide batched gather-sum of 32-float rows: indices clamped to slot 0 for
// the out-of-range tail (address always valid), loads issued back-to-back
// (MLP=8), masked via select, tree-added.
__device__ __forceinline__ float gather8(const float* __restrict__ rows,
                                         const int* __restrict__ bsp,
                                         int dc, int lane) {
    float acc = 0.0f;
    for (int base = 0; base < dc; base += 8) {
        int rem = dc - base;
        int idx[8];
        #pragma unroll
        for (int u = 0; u < 8; u++)
            idx[u] = bsp[base + (u < rem ? u : 0)];
        float v[8];
        #pragma unroll
        for (int u = 0; u < 8; u++)
            v[u] = rows[(size_t)idx[u] * 32 + lane];
        #pragma unroll
        for (int u = 0; u < 8; u++)
            if (u >= rem) v[u] = 0.0f;
        acc += ((v[0] + v[1]) + (v[2] + v[3])) + ((v[4] + v[5]) + (v[6] + v[7]));
    }
    return acc;
}

// e2n: warp per node, lane = feature; batched gather of edge feature rows
__global__ void e2n_kernel(const float* __restrict__ edge_feat) {
    int gw   = (blockIdx.x * blockDim.x + threadIdx.x) >> 5;
    int lane = threadIdx.x & 31;
    if (gw >= NN) return;
    int dc = min(g_cnt[gw], CAP);
    const int* bp = g_bkt + (size_t)gw * CAP;
    g_e2n[(size_t)gw * 32 + lane] = gather8(edge_feat, bp, dc, lane);
}

// z0 = [node_feat | e2n] @ W0  — register-tiled block GEMM (R10 shape).
// block = 256 threads, 128 nodes; thread tile = 4 nodes x 4 channels.
__global__ void mm0_kernel(const float* __restrict__ nf,
                           const float* __restrict__ W0) {
    __shared__ float Ws[160 * 32];       // full weight matrix, 20KB
    __shared__ float Xs[32][133];        // f-major transposed chunk, pad=133
    int tid = threadIdx.x;
    for (int i = tid; i < 160 * 32; i += 256) Ws[i] = W0[i];

    int nbase = blockIdx.x * 128;
    int chg = (tid & 7) * 4;             // channel group 0,4,...,28
    int ng  = (tid >> 3) * 4;            // node group 0,4,...,124
    int f    = tid & 31;                 // lane = feature (coalesced LDG)
    int nrow = tid >> 5;                 // 0..7

    float acc[4][4];
    #pragma unroll
    for (int m = 0; m < 4; m++)
        #pragma unroll
        for (int k = 0; k < 4; k++) acc[m][k] = 0.0f;

    for (int c = 0; c < 5; c++) {
        __syncthreads();
        int fg = c * 32 + f;
        #pragma unroll
        for (int i = 0; i < 16; i++) {
            int n = nrow + i * 8;
            Xs[f][n] = (fg < 128)
                ? nf[(size_t)(nbase + n) * 128 + fg]
                : g_e2n[(size_t)(nbase + n) * 32 + (fg - 128)];
        }
        __syncthreads();
        #pragma unroll
        for (int f2 = 0; f2 < 32; f2++) {
            float4 w = *(const float4*)&Ws[(c * 32 + f2) * 32 + chg];
            float x0 = Xs[f2][ng + 0];
            float x1 = Xs[f2][ng + 1];
            float x2 = Xs[f2][ng + 2];
            float x3 = Xs[f2][ng + 3];
            acc[0][0] += x0 * w.x; acc[0][1] += x0 * w.y;
            acc[0][2] += x0 * w.z; acc[0][3] += x0 * w.w;
            acc[1][0] += x1 * w.x; acc[1][1] += x1 * w.y;
            acc[1][2] += x1 * w.z; acc[1][3] += x1 * w.w;
            acc[2][0] += x2 * w.x; acc[2][1] += x2 * w.y;
            acc[2][2] += x2 * w.z; acc[2][3] += x2 * w.w;
            acc[3][0] += x3 * w.x; acc[3][1] += x3 * w.y;
            acc[3][2] += x3 * w.z; acc[3][3] += x3 * w.w;
        }
    }
    #pragma unroll
    for (int m = 0; m < 4; m++) {
        float4 o = make_float4(acc[m][0], acc[m][1], acc[m][2], acc[m][3]);
        *(float4*)&g_za[(size_t)(nbase + ng + m) * 32 + chg] = o;
    }
}

// pool(z)+z -> +bias -> /deg -> tanh -> feat slice, then block-tiled GEMM
// z_next = V @ Wn through smem. 64 nodes per 256-thread block. Gather is
// 8-wide batched (MLP=8).
__global__ void pool_kernel(int zin_which, int zout_which,
                            const float* __restrict__ bcur,
                            const float* __restrict__ Wn,
                            int foff, int scalar_next) {
    __shared__ float Ws[32 * 32];
    __shared__ float Vs[PNB][33];
    __shared__ float bs[32];
    __shared__ float sw[32];
    int tid = threadIdx.x;
    if (tid < 32) {
        bs[tid] = bcur[tid];
        if (scalar_next) sw[tid] = Wn[tid];
    }
    if (!scalar_next)
        for (int i = tid; i < 32 * 32; i += 256) Ws[i] = Wn[i];
    __syncthreads();

    const float* zin = zbuf(zin_which);
    int lane = tid & 31;
    int w    = tid >> 5;
    int nbase = blockIdx.x * PNB;

    #pragma unroll
    for (int r = 0; r < 8; r++) {
        int node = nbase + w * 8 + r;
        int deg = g_cnt[node];
        int dc  = min(deg, CAP);
        const int* bsp = g_bsrc + (size_t)node * CAP;
        float acc = zin[(size_t)node * 32 + lane]     // self term (A + I)
                  + gather8(zin, bsp, dc, lane);
        float v = tanhf((acc + bs[lane]) / (float)(deg + 1));
        g_feat[(size_t)node * DD + foff + lane] = v;
        if (scalar_next) {
            float p = v * sw[lane];
            #pragma unroll
            for (int o = 16; o > 0; o >>= 1)
                p += __shfl_xor_sync(0xffffffffu, p, o);
            if (lane == 0) g_z3[node] = p;
        } else {
            Vs[w * 8 + r][lane] = v;
        }
    }
    if (scalar_next) return;
    __syncthreads();

    float* zout = zbuf(zout_which);
    int chg = (tid & 7) * 4;     // 4 output channels
    int n0  = (tid >> 3) * 2;    // 2 nodes
    float a[2][4] = {{0.f,0.f,0.f,0.f},{0.f,0.f,0.f,0.f}};
    #pragma unroll
    for (int t = 0; t < 32; t++) {
        float4 w4 = *(const float4*)&Ws[t * 32 + chg];
        float x0 = Vs[n0][t];
        float x1 = Vs[n0 + 1][t];
        a[0][0] += x0 * w4.x; a[0][1] += x0 * w4.y;
        a[0][2] += x0 * w4.z; a[0][3] += x0 * w4.w;
        a[1][0] += x1 * w4.x; a[1][1] += x1 * w4.y;
        a[1][2] += x1 * w4.z; a[1][3] += x1 * w4.w;
    }
    *(float4*)&zout[(size_t)(nbase + n0) * 32 + chg] =
        make_float4(a[0][0], a[0][1], a[0][2], a[0][3]);
    *(float4*)&zout[(size_t)(nbase + n0 + 1) * 32 + chg] =
        make_float4(a[1][0], a[1][1], a[1][2], a[1][3]);
}

// final hop: scalar pooling of z3, thread per node, batched loads for MLP
__global__ void pool_scalar_kernel(const float* __restrict__ b3) {
    int n = blockIdx.x * blockDim.x + threadIdx.x;
    if (n >= NN) return;
    int deg = g_cnt[n];
    int dc  = min(deg, CAP);
    const int* bsp = g_bsrc + (size_t)n * CAP;
    float acc = g_z3[n];
    for (int base = 0; base < dc; base += 8) {
        int rem = dc - base;
        int idx[8];
        #pragma unroll
        for (int u = 0; u < 8; u++)
            idx[u] = bsp[base + (u < rem ? u : 0)];
        float v[8];
        #pragma unroll
        for (int u = 0; u < 8; u++)
            v[u] = g_z3[idx[u]];
        #pragma unroll
        for (int u = 0; u < 8; u++)
            if (u >= rem) v[u] = 0.0f;
        acc += ((v[0] + v[1]) + (v[2] + v[3])) + ((v[4] + v[5]) + (v[6] + v[7]));
    }
    g_feat[(size_t)n * DD + 96] = tanhf((acc + b3[0]) / (float)(deg + 1));
}

// ---------------------------------------------------------------------------
// one block per graph: register-resident stable top-k (warp-shuffle argmax)
// -> gather -> conv1 -> relu -> maxpool2 -> conv2 -> relu -> dense -> relu
__global__ void tail_kernel(const float* __restrict__ w1, const float* __restrict__ b1,
                            const float* __restrict__ w2, const float* __restrict__ b2,
                            const float* __restrict__ wo, const float* __restrict__ bo,
                            float* __restrict__ out) {
    __shared__ float wv[8];
    __shared__ int   wi[8];
    __shared__ int   topi[KK];
    __shared__ float sp[KK * DD];
    __shared__ float s_w1[16 * DD];
    __shared__ float s_w2[32 * 16 * 5];
    __shared__ float o1[16 * 30];
    __shared__ float pl[16 * 15];
    __shared__ float o2[32 * 11];

    int b = blockIdx.x;
    int tid = threadIdx.x;
    int lane = tid & 31;

    // scores live in registers: thread owns indices tid + q*256
    float r[4];
    #pragma unroll
    for (int q = 0; q < 4; q++)
        r[q] = g_feat[(size_t)(b * NPG + tid + q * 256) * DD + 96];
    for (int i = tid; i < 16 * DD; i += 256) s_w1[i] = w1[i];
    for (int i = tid; i < 32 * 16 * 5; i += 256) s_w2[i] = w2[i];
    __syncthreads();

    // iterative argmax, stable (lowest index wins on ties)
    for (int k = 0; k < KK; k++) {
        float bv = -2.0f; int bi = NPG;
        #pragma unroll
        for (int q = 0; q < 4; q++) {        // indices increase with q
            if (r[q] > bv) { bv = r[q]; bi = tid + q * 256; }
        }
        #pragma unroll
        for (int o = 16; o > 0; o >>= 1) {
            float ov = __shfl_down_sync(0xffffffffu, bv, o);
            int   oi = __shfl_down_sync(0xffffffffu, bi, o);
            if (ov > bv || (ov == bv && oi < bi)) { bv = ov; bi = oi; }
        }
        if (lane == 0) { wv[tid >> 5] = bv; wi[tid >> 5] = bi; }
        __syncthreads();
        if (tid == 0) {
            #pragma unroll
            for (int u = 1; u < 8; u++)
                if (wv[u] > bv || (wv[u] == bv && wi[u] < bi)) { bv = wv[u]; bi = wi[u]; }
            topi[k] = bi;
        }
        __syncthreads();
        int bsel = topi[k];
        if ((bsel & 255) == tid) r[bsel >> 8] = -3.0f;   // remove selected
    }

    // gather the 30 selected rows
    for (int i = tid; i < KK * DD; i += 256) {
        int k = i / DD;
        int d = i - k * DD;
        sp[i] = g_feat[(size_t)(b * NPG + topi[k]) * DD + d];
    }
    __syncthreads();

    // conv1: [16, 30]
    for (int i = tid; i < 16 * 30; i += 256) {
        int c = i / 30;
        int pos = i - c * 30;
        float s = b1[c];
        for (int d = 0; d < DD; d++) s += sp[pos * DD + d] * s_w1[c * DD + d];
        o1[i] = fmaxf(s, 0.0f);
    }
    __syncthreads();

    // maxpool(2,2) -> [16, 15]
    for (int i = tid; i < 16 * 15; i += 256) {
        int c = i / 15;
        int pos = i - c * 15;
        pl[i] = fmaxf(o1[c * 30 + 2 * pos], o1[c * 30 + 2 * pos + 1]);
    }
    __syncthreads();

    // conv2: [32, 11]
    for (int i = tid; i < 32 * 11; i += 256) {
        int c = i / 11;
        int pos = i - c * 11;
        float s = b2[c];
        for (int ci = 0; ci < 16; ci++)
            for (int t = 0; t < 5; t++)
                s += pl[ci * 15 + pos + t] * s_w2[(c * 16 + ci) * 5 + t];
        o2[i] = fmaxf(s, 0.0f);
    }
    __syncthreads();

    // dense -> [2], relu
    if (tid < 2) {
        float s = bo[tid];
        for (int j = 0; j < 352; j++) s += o2[j] * wo[j * 2 + tid];
        out[b * 2 + tid] = fmaxf(s, 0.0f);
    }
}

// ---------------------------------------------------------------------------
extern "C" void kernel_launch(void* const* d_in, const int* in_sizes, int n_in,
                              void* d_out, int out_size) {
    const float* node_feat = (const float*)d_in[0];
    const float* edge_feat = (const float*)d_in[1];
    const int*   eidx      = (const int*)d_in[2];
    const int*   src = eidx;
    const int*   dst = eidx + EE;
    const float* W0 = (const float*)d_in[3];  const float* b0 = (const float*)d_in[4];
    const float* W1 = (const float*)d_in[5];  const float* b1 = (const float*)d_in[6];
    const float* W2 = (const float*)d_in[7];  const float* b2 = (const float*)d_in[8];
    const float* W3 = (const float*)d_in[9];  const float* b3 = (const float*)d_in[10];
    const float* w_conv1 = (const float*)d_in[11];
    const float* b_conv1 = (const float*)d_in[12];
    const float* w_conv2 = (const float*)d_in[13];
    const float* b_conv2 = (const float*)d_in[14];
    const float* w_out   = (const float*)d_in[15];
    const float* b_out   = (const float*)d_in[16];
    float* out = (float*)d_out;

    const int TPB = 256;
    const int warp_grid = (NN * 32 + TPB - 1) / TPB;   // warp-per-node kernels
    const int pool_grid = NN / PNB;                    // 2048 blocks

    zero_cnt_kernel<<<(NN + TPB - 1) / TPB, TPB>>>();
    fill_kernel<<<(EE + TPB - 1) / TPB, TPB>>>(src, dst);
    e2n_kernel<<<warp_grid, TPB>>>(edge_feat);
    mm0_kernel<<<NN / 128, TPB>>>(node_feat, W0);             // -> g_za
    pool_kernel<<<pool_grid, TPB>>>(0, 1, b0, W1,  0, 0);     // za->zb
    pool_kernel<<<pool_grid, TPB>>>(1, 0, b1, W2, 32, 0);     // zb->za
    pool_kernel<<<pool_grid, TPB>>>(0, 0, b2, W3, 64, 1);     // za->g_z3
    pool_scalar_kernel<<<(NN + TPB - 1) / TPB, TPB>>>(b3);    // hop3
    tail_kernel<<<BB, TPB>>>(w_conv1, b_conv1, w_conv2, b_conv2,
                             w_out, b_out, out);
}

// round 17
// speedup vs baseline: 1.0308x; 1.0043x over previous
#include <cuda_runtime.h>
#include <math.h>

#define NN   131072      // total nodes
#define EE   1048576     // total edges
#define BB   128         // graphs
#define NPG  1024        // nodes per graph
#define DD   97          // total latent dim
#define KK   30          // sort-pool k
#define CAP  64          // max in-degree bucket capacity (Poisson(8): P(>64) ~ 0)
#define PNB  64          // nodes per block in pool kernel

// ---- scratch (device globals; no allocation allowed) ----
__device__ int   g_cnt[NN];                 // in-degree (fill cursor)
__device__ int   g_bkt [(size_t)NN * CAP];  // buckets: edge id by dst (for e2n)
__device__ int   g_bsrc[(size_t)NN * CAP];  // buckets: src node by dst (for pools)
__device__ float g_e2n[(size_t)NN * 32];    // pooled edge features per node
__device__ float g_za [(size_t)NN * 32];    // z ping
__device__ float g_zb [(size_t)NN * 32];    // z pong
__device__ float g_z3 [NN];                 // scalar z for hop 3
__device__ float g_feat[(size_t)NN * DD];   // concatenated hop outputs

// buffer selectors resolved in DEVICE code only
__device__ __forceinline__ float* zbuf(int which) {
    return which == 0 ? g_za : g_zb;
}

// ---------------------------------------------------------------------------
__global__ void zero_cnt_kernel() {
    int i = blockIdx.x * blockDim.x + threadIdx.x;
    if (i < NN) g_cnt[i] = 0;
}

// place each edge into its destination bucket; also cache src id
__global__ void fill_kernel(const int* __restrict__ src,
                            const int* __restrict__ dst) {
    int e = blockIdx.x * blockDim.x + threadIdx.x;
    if (e >= EE) return;
    int d = dst[e];
    int pos = atomicAdd(&g_cnt[d], 1);
    if (pos < CAP) {
        g_bkt [(size_t)d * CAP + pos] = e;
        g_bsrc[(size_t)d * CAP + pos] = src[e];
    }
}

// e2n: warp per node, lane = feature; gather-sum incident edge feature rows
// (exact R10 form — serial loop, minimal registers, occupancy-driven)
__global__ void e2n_kernel(const float* __restrict__ edge_feat) {
    int gw   = (blockIdx.x * blockDim.x + threadIdx.x) >> 5;
    int lane = threadIdx.x & 31;
    if (gw >= NN) return;
    int dc = min(g_cnt[gw], CAP);
    const int* bp = g_bkt + (size_t)gw * CAP;
    float acc = 0.0f;
    for (int i = 0; i < dc; i++) {
        int e = bp[i];
        acc += edge_feat[(size_t)e * 32 + lane];
    }
    g_e2n[(size_t)gw * 32 + lane] = acc;
}

// z0 = [node_feat | e2n] @ W0  — register-tiled block GEMM (R10 tile shape),
// grid-stride over 2 tiles per block: 512 blocks, weights loaded once.
__global__ void mm0_kernel(const float* __restrict__ nf,
                           const float* __restrict__ W0) {
    __shared__ float Ws[160 * 32];       // full weight matrix, 20KB
    __shared__ float Xs[32][133];        // f-major transposed chunk, pad=133
    int tid = threadIdx.x;
    for (int i = tid; i < 160 * 32; i += 256) Ws[i] = W0[i];

    int chg = (tid & 7) * 4;             // channel group 0,4,...,28
    int ng  = (tid >> 3) * 4;            // node group 0,4,...,124
    int f    = tid & 31;                 // lane = feature (coalesced LDG)
    int nrow = tid >> 5;                 // 0..7

    for (int t = 0; t < 2; t++) {
        int nbase = (blockIdx.x * 2 + t) * 128;

        float acc[4][4];
        #pragma unroll
        for (int m = 0; m < 4; m++)
            #pragma unroll
            for (int k = 0; k < 4; k++) acc[m][k] = 0.0f;

        for (int c = 0; c < 5; c++) {
            __syncthreads();
            int fg = c * 32 + f;
            #pragma unroll
            for (int i = 0; i < 16; i++) {
                int n = nrow + i * 8;
                Xs[f][n] = (fg < 128)
                    ? nf[(size_t)(nbase + n) * 128 + fg]
                    : g_e2n[(size_t)(nbase + n) * 32 + (fg - 128)];
            }
            __syncthreads();
            #pragma unroll
            for (int f2 = 0; f2 < 32; f2++) {
                float4 w = *(const float4*)&Ws[(c * 32 + f2) * 32 + chg];
                float x0 = Xs[f2][ng + 0];
                float x1 = Xs[f2][ng + 1];
                float x2 = Xs[f2][ng + 2];
                float x3 = Xs[f2][ng + 3];
                acc[0][0] += x0 * w.x; acc[0][1] += x0 * w.y;
                acc[0][2] += x0 * w.z; acc[0][3] += x0 * w.w;
                acc[1][0] += x1 * w.x; acc[1][1] += x1 * w.y;
                acc[1][2] += x1 * w.z; acc[1][3] += x1 * w.w;
                acc[2][0] += x2 * w.x; acc[2][1] += x2 * w.y;
                acc[2][2] += x2 * w.z; acc[2][3] += x2 * w.w;
                acc[3][0] += x3 * w.x; acc[3][1] += x3 * w.y;
                acc[3][2] += x3 * w.z; acc[3][3] += x3 * w.w;
            }
        }
        #pragma unroll
        for (int m = 0; m < 4; m++) {
            float4 o = make_float4(acc[m][0], acc[m][1], acc[m][2], acc[m][3]);
            *(float4*)&g_za[(size_t)(nbase + ng + m) * 32 + chg] = o;
        }
    }
}

// pool(z)+z -> +bias -> /deg -> tanh -> feat slice, then block-tiled GEMM
// z_next = V @ Wn through smem. 64 nodes per 256-thread block.
// Gather loop paired 2-deep (MLP=2, ~+4 regs only).
__global__ void pool_kernel(int zin_which, int zout_which,
                            const float* __restrict__ bcur,
                            const float* __restrict__ Wn,
                            int foff, int scalar_next) {
    __shared__ float Ws[32 * 32];
    __shared__ float Vs[PNB][33];
    __shared__ float bs[32];
    __shared__ float sw[32];
    int tid = threadIdx.x;
    if (tid < 32) {
        bs[tid] = bcur[tid];
        if (scalar_next) sw[tid] = Wn[tid];
    }
    if (!scalar_next)
        for (int i = tid; i < 32 * 32; i += 256) Ws[i] = Wn[i];
    __syncthreads();

    const float* zin = zbuf(zin_which);
    int lane = tid & 31;
    int w    = tid >> 5;
    int nbase = blockIdx.x * PNB;

    #pragma unroll
    for (int r = 0; r < 8; r++) {
        int node = nbase + w * 8 + r;
        int deg = g_cnt[node];
        int dc  = min(deg, CAP);
        const int* bsp = g_bsrc + (size_t)node * CAP;
        float acc = zin[(size_t)node * 32 + lane];    // self term (A + I)
        int i = 0;
        for (; i + 2 <= dc; i += 2) {                 // 2-deep pairing
            int s0 = bsp[i];
            int s1 = bsp[i + 1];
            float v0 = zin[(size_t)s0 * 32 + lane];
            float v1 = zin[(size_t)s1 * 32 + lane];
            acc += v0; acc += v1;
        }
        if (i < dc)
            acc += zin[(size_t)bsp[i] * 32 + lane];
        float v = tanhf((acc + bs[lane]) / (float)(deg + 1));
        g_feat[(size_t)node * DD + foff + lane] = v;
        if (scalar_next) {
            float p = v * sw[lane];
            #pragma unroll
            for (int o = 16; o > 0; o >>= 1)
                p += __shfl_xor_sync(0xffffffffu, p, o);
            if (lane == 0) g_z3[node] = p;
        } else {
            Vs[w * 8 + r][lane] = v;
        }
    }
    if (scalar_next) return;
    __syncthreads();

    float* zout = zbuf(zout_which);
    int chg = (tid & 7) * 4;     // 4 output channels
    int n0  = (tid >> 3) * 2;    // 2 nodes
    float a[2][4] = {{0.f,0.f,0.f,0.f},{0.f,0.f,0.f,0.f}};
    #pragma unroll
    for (int t = 0; t < 32; t++) {
        float4 w4 = *(const float4*)&Ws[t * 32 + chg];
        float x0 = Vs[n0][t];
        float x1 = Vs[n0 + 1][t];
        a[0][0] += x0 * w4.x; a[0][1] += x0 * w4.y;
        a[0][2] += x0 * w4.z; a[0][3] += x0 * w4.w;
        a[1][0] += x1 * w4.x; a[1][1] += x1 * w4.y;
        a[1][2] += x1 * w4.z; a[1][3] += x1 * w4.w;
    }
    *(float4*)&zout[(size_t)(nbase + n0) * 32 + chg] =
        make_float4(a[0][0], a[0][1], a[0][2], a[0][3]);
    *(float4*)&zout[(size_t)(nbase + n0 + 1) * 32 + chg] =
        make_float4(a[1][0], a[1][1], a[1][2], a[1][3]);
}

// final hop: scalar pooling of z3, thread per node (exact R10 form)
__global__ void pool_scalar_kernel(const float* __restrict__ b3) {
    int n = blockIdx.x * blockDim.x + threadIdx.x;
    if (n >= NN) return;
    int deg = g_cnt[n];
    int dc  = min(deg, CAP);
    const int* bsp = g_bsrc + (size_t)n * CAP;
    float acc = g_z3[n];
    for (int i = 0; i < dc; i++) acc += g_z3[bsp[i]];
    g_feat[(size_t)n * DD + 96] = tanhf((acc + b3[0]) / (float)(deg + 1));
}

// ---------------------------------------------------------------------------
// one block per graph: register-resident stable top-k (warp-shuffle argmax)
// -> gather -> conv1 -> relu -> maxpool2 -> conv2 -> relu -> dense -> relu
__global__ void tail_kernel(const float* __restrict__ w1, const float* __restrict__ b1,
                            const float* __restrict__ w2, const float* __restrict__ b2,
                            const float* __restrict__ wo, const float* __restrict__ bo,
                            float* __restrict__ out) {
    __shared__ float wv[8];
    __shared__ int   wi[8];
    __shared__ int   topi[KK];
    __shared__ float sp[KK * DD];
    __shared__ float s_w1[16 * DD];
    __shared__ float s_w2[32 * 16 * 5];
    __shared__ float o1[16 * 30];
    __shared__ float pl[16 * 15];
    __shared__ float o2[32 * 11];

    int b = blockIdx.x;
    int tid = threadIdx.x;
    int lane = tid & 31;

    // scores live in registers: thread owns indices tid + q*256
    float r[4];
    #pragma unroll
    for (int q = 0; q < 4; q++)
        r[q] = g_feat[(size_t)(b * NPG + tid + q * 256) * DD + 96];
    for (int i = tid; i < 16 * DD; i += 256) s_w1[i] = w1[i];
    for (int i = tid; i < 32 * 16 * 5; i += 256) s_w2[i] = w2[i];
    __syncthreads();

    // iterative argmax, stable (lowest index wins on ties)
    for (int k = 0; k < KK; k++) {
        float bv = -2.0f; int bi = NPG;
        #pragma unroll
        for (int q = 0; q < 4; q++) {        // indices increase with q
            if (r[q] > bv) { bv = r[q]; bi = tid + q * 256; }
        }
        #pragma unroll
        for (int o = 16; o > 0; o >>= 1) {
            float ov = __shfl_down_sync(0xffffffffu, bv, o);
            int   oi = __shfl_down_sync(0xffffffffu, bi, o);
            if (ov > bv || (ov == bv && oi < bi)) { bv = ov; bi = oi; }
        }
        if (lane == 0) { wv[tid >> 5] = bv; wi[tid >> 5] = bi; }
        __syncthreads();
        if (tid == 0) {
            #pragma unroll
            for (int u = 1; u < 8; u++)
                if (wv[u] > bv || (wv[u] == bv && wi[u] < bi)) { bv = wv[u]; bi = wi[u]; }
            topi[k] = bi;
        }
        __syncthreads();
        int bsel = topi[k];
        if ((bsel & 255) == tid) r[bsel >> 8] = -3.0f;   // remove selected
    }

    // gather the 30 selected rows
    for (int i = tid; i < KK * DD; i += 256) {
        int k = i / DD;
        int d = i - k * DD;
        sp[i] = g_feat[(size_t)(b * NPG + topi[k]) * DD + d];
    }
    __syncthreads();

    // conv1: [16, 30]
    for (int i = tid; i < 16 * 30; i += 256) {
        int c = i / 30;
        int pos = i - c * 30;
        float s = b1[c];
        for (int d = 0; d < DD; d++) s += sp[pos * DD + d] * s_w1[c * DD + d];
        o1[i] = fmaxf(s, 0.0f);
    }
    __syncthreads();

    // maxpool(2,2) -> [16, 15]
    for (int i = tid; i < 16 * 15; i += 256) {
        int c = i / 15;
        int pos = i - c * 15;
        pl[i] = fmaxf(o1[c * 30 + 2 * pos], o1[c * 30 + 2 * pos + 1]);
    }
    __syncthreads();

    // conv2: [32, 11]
    for (int i = tid; i < 32 * 11; i += 256) {
        int c = i / 11;
        int pos = i - c * 11;
        float s = b2[c];
        for (int ci = 0; ci < 16; ci++)
            for (int t = 0; t < 5; t++)
                s += pl[ci * 15 + pos + t] * s_w2[(c * 16 + ci) * 5 + t];
        o2[i] = fmaxf(s, 0.0f);
    }
    __syncthreads();

    // dense -> [2], relu
    if (tid < 2) {
        float s = bo[tid];
        for (int j = 0; j < 352; j++) s += o2[j] * wo[j * 2 + tid];
        out[b * 2 + tid] = fmaxf(s, 0.0f);
    }
}

// ---------------------------------------------------------------------------
extern "C" void kernel_launch(void* const* d_in, const int* in_sizes, int n_in,
                              void* d_out, int out_size) {
    const float* node_feat = (const float*)d_in[0];
    const float* edge_feat = (const float*)d_in[1];
    const int*   eidx      = (const int*)d_in[2];
    const int*   src = eidx;
    const int*   dst = eidx + EE;
    const float* W0 = (const float*)d_in[3];  const float* b0 = (const float*)d_in[4];
    const float* W1 = (const float*)d_in[5];  const float* b1 = (const float*)d_in[6];
    const float* W2 = (const float*)d_in[7];  const float* b2 = (const float*)d_in[8];
    const float* W3 = (const float*)d_in[9];  const float* b3 = (const float*)d_in[10];
    const float* w_conv1 = (const float*)d_in[11];
    const float* b_conv1 = (const float*)d_in[12];
    const float* w_conv2 = (const float*)d_in[13];
    const float* b_conv2 = (const float*)d_in[14];
    const float* w_out   = (const float*)d_in[15];
    const float* b_out   = (const float*)d_in[16];
    float* out = (float*)d_out;

    const int TPB = 256;
    const int warp_grid = (NN * 32 + TPB - 1) / TPB;   // warp-per-node kernels
    const int pool_grid = NN / PNB;                    // 2048 blocks

    zero_cnt_kernel<<<(NN + TPB - 1) / TPB, TPB>>>();
    fill_kernel<<<(EE + TPB - 1) / TPB, TPB>>>(src, dst);
    e2n_kernel<<<warp_grid, TPB>>>(edge_feat);
    mm0_kernel<<<NN / 256, TPB>>>(node_feat, W0);             // 512 blocks, 2 tiles each
    pool_kernel<<<pool_grid, TPB>>>(0, 1, b0, W1,  0, 0);     // za->zb
    pool_kernel<<<pool_grid, TPB>>>(1, 0, b1, W2, 32, 0);     // zb->za
    pool_kernel<<<pool_grid, TPB>>>(0, 0, b2, W3, 64, 1);     // za->g_z3
    pool_scalar_kernel<<<(NN + TPB - 1) / TPB, TPB>>>(b3);    // hop3
    tail_kernel<<<BB, TPB>>>(w_conv1, b_conv1, w_conv2, b_conv2,
                             w_out, b_out, out);
}